// round 16
// baseline (speedup 1.0000x reference)
#include <cuda_runtime.h>
#include <cstdint>

#define RES0 2048
#define RES1 1024
#define NPTS 2097152
#define NITER 8

// g0: plain per-texel code table (8ch x 4bit -> u32). 16 MB.
__device__ uint32_t g_code0[(size_t)RES0 * RES0];
// g1: quad table, entry (y,x) = codes of 4 clamped corners. 16 MB.
__device__ uint4 g_quad1[(size_t)RES1 * RES1];
// Total 32 MB -> fully L2-resident against evict-first streams (proven R11).

__device__ __forceinline__ uint32_t quant_code(float v) {
    float t = __fmul_rn(__fadd_rn(v, 0.46875f), 16.0f);
    int c = __float2int_rn(t);
    return (uint32_t)max(0, min(15, c));
}

// Exact dequant of nibble i: c/16 - 15/32.
__device__ __forceinline__ float dec(uint32_t p, int i) {
    uint32_t t = (i < 5) ? (p << (19 - 4 * i)) : (p >> (4 * i - 19));
    uint32_t u = (t & 0x00780000u) | 0x3F800000u;
    return __uint_as_float(u) - 1.46875f;
}

// Partial dequant: 1 + c/16 (no subtraction).
__device__ __forceinline__ float decu(uint32_t p, int i) {
    uint32_t t = (i < 5) ? (p << (19 - 4 * i)) : (p >> (4 * i - 19));
    uint32_t u = (t & 0x00780000u) | 0x3F800000u;
    return __uint_as_float(u);
}

__device__ __forceinline__ uint32_t smem_u32(const void* p) {
    return (uint32_t)__cvta_generic_to_shared(p);
}
__device__ __forceinline__ void cp_async4(uint32_t dst, const void* src) {
    asm volatile("cp.async.ca.shared.global [%0], [%1], 4;" :: "r"(dst), "l"(src));
}
__device__ __forceinline__ void cp_async16(uint32_t dst, const void* src) {
    asm volatile("cp.async.cg.shared.global [%0], [%1], 16;" :: "r"(dst), "l"(src));
}
#define CP_COMMIT() asm volatile("cp.async.commit_group;" ::: "memory")
#define CP_WAIT1()  asm volatile("cp.async.wait_group 1;" ::: "memory")

// ---------------- fused pack: both grids in ONE launch (R11, proven) --------
__device__ __forceinline__ void pack_body0(const float* __restrict__ g, int blk) {
    int i4 = (blk * 512 + threadIdx.x) * 4;
    uint32_t c0 = 0, c1 = 0, c2 = 0, c3 = 0;
#pragma unroll
    for (int ch = 0; ch < 8; ch++) {
        float4 v = __ldcs((const float4*)(g + (size_t)ch * RES0 * RES0 + i4));
        c0 |= quant_code(v.x) << (4 * ch);
        c1 |= quant_code(v.y) << (4 * ch);
        c2 |= quant_code(v.z) << (4 * ch);
        c3 |= quant_code(v.w) << (4 * ch);
    }
    *(uint4*)(g_code0 + i4) = make_uint4(c0, c1, c2, c3);
}

__device__ __forceinline__ void pack_body1(const float* __restrict__ g, int blk) {
    __shared__ uint32_t sc[17][33];
    int bx = (blk % (RES1 / 32)) * 32;
    int by = (blk / (RES1 / 32)) * 16;
    int tid = threadIdx.x;

    for (int p = tid; p < 17 * 33; p += 512) {
        int ly = p / 33, lx = p - ly * 33;
        int gx = min(bx + lx, RES1 - 1);
        int gy = min(by + ly, RES1 - 1);
        size_t base = (size_t)gy * RES1 + gx;
        uint32_t pk = 0;
#pragma unroll
        for (int c = 0; c < 8; c++) {
            float v = __ldcs(g + (size_t)c * RES1 * RES1 + base);
            pk |= quant_code(v) << (4 * c);
        }
        sc[ly][lx] = pk;
    }
    __syncthreads();

    int lx = tid & 31, ly = tid >> 5;
    g_quad1[(size_t)(by + ly) * RES1 + bx + lx] =
        make_uint4(sc[ly][lx], sc[ly][lx + 1], sc[ly + 1][lx], sc[ly + 1][lx + 1]);
}

#define NBLK0 (RES0 * RES0 / 4 / 512)
#define NBLK1 ((RES1 / 32) * (RES1 / 16))

__global__ __launch_bounds__(512) void pack_all(const float* __restrict__ g0,
                                                const float* __restrict__ g1) {
    int b = blockIdx.x;
    if (b < NBLK0) pack_body0(g0, b);
    else           pack_body1(g1, b - NBLK0);
}

// ---------------- sample: cp.async prefetch pipeline, depth 1 ---------------
// Prefetch slot (32B): [4 corner codes (cp.async 4B x4)][q1 (cp.async 16B)].
// Double-buffered; the warp only ever waits on the group issued a full
// iteration (~2000 cyc of compute+stores) earlier.
__global__ __launch_bounds__(256) void sample_kernel(const float2* __restrict__ uv,
                                                     float* __restrict__ out) {
    __shared__ __align__(16) uint32_t pbuf[2][8][32][8];
    __shared__ __align__(16) float ffbuf[8][32][12];

    int tid = threadIdx.x;
    int lane = tid & 31;
    int warp = tid >> 5;
    int ptbase = blockIdx.x * (NITER * 256);

    uint32_t slot0 = smem_u32(&pbuf[0][warp][lane][0]);
    uint32_t slot1 = smem_u32(&pbuf[1][warp][lane][0]);

    // Prefetch issue: compute indices for point pi, launch 5 cp.asyncs.
    auto prefetch = [&](int pi, uint32_t slot, float& ix, float& iy,
                        int& qx0, int& qy0) {
        float2 p = __ldcs(&uv[pi]);
        float px = fmaf(p.x, 2048.0f, -0.5f);
        float py = fmaf(p.y, 2048.0f, -0.5f);
        int x0 = min(max((int)floorf(px), 0), RES0 - 2);
        int y0 = min(max((int)floorf(py), 0), RES0 - 2);
        ix = fmaf(p.x, 1024.0f, -0.5f);
        iy = fmaf(p.y, 1024.0f, -0.5f);
        qx0 = (int)floorf(ix);
        qy0 = (int)floorf(iy);
        int cx = max(qx0, 0);
        int cy = max(qy0, 0);
        const uint32_t* c0 = g_code0 + (size_t)y0 * RES0 + x0;
        cp_async4(slot + 0,  c0);
        cp_async4(slot + 4,  c0 + 1);
        cp_async4(slot + 8,  c0 + RES0);
        cp_async4(slot + 12, c0 + RES0 + 1);
        cp_async16(slot + 16, &g_quad1[(size_t)cy * RES1 + cx]);
    };

    float cix, ciy; int cqx, cqy;
    prefetch(ptbase + tid, slot0, cix, ciy, cqx, cqy);
    CP_COMMIT();

    for (int it = 0; it < NITER; it++) {
        int cur = it & 1;
        float nix, niy; int nqx, nqy;
        if (it + 1 < NITER)
            prefetch(ptbase + (it + 1) * 256 + tid, cur ? slot0 : slot1,
                     nix, niy, nqx, nqy);
        CP_COMMIT();           // empty group on last iter (keeps wait uniform)
        CP_WAIT1();            // completes the group for iteration `it`

        // ---- consume iteration it ----
        uint32_t myslot = cur ? slot1 : slot0;
        uint4 q1;
        asm volatile("ld.shared.v4.u32 {%0,%1,%2,%3}, [%4];"
                     : "=r"(q1.x), "=r"(q1.y), "=r"(q1.z), "=r"(q1.w)
                     : "r"(myslot + 16));

        float fx0 = floorf(cix), fy0 = floorf(ciy);
        float wx1 = __fsub_rn(cix, fx0), wx0 = __fsub_rn(1.0f, wx1);
        float wy1 = __fsub_rn(ciy, fy0), wy0 = __fsub_rn(1.0f, wy1);
        float wx0m = (cqx >= 0) ? wx0 : 0.0f;
        float wx1m = (cqx + 1 <= RES1 - 1) ? wx1 : 0.0f;
        float wy0m = (cqy >= 0) ? wy0 : 0.0f;
        float wy1m = (cqy + 1 <= RES1 - 1) ? wy1 : 0.0f;
        float w00 = wx0m * wy0m;
        float w10 = wx1m * wy0m;
        float w01 = wx0m * wy1m;
        float w11 = wx1m * wy1m;
        float wsum = ((w00 + w10) + w01) + w11;
        float base = -1.46875f * wsum;

        uint32_t p00 = q1.x;
        uint32_t p10 = (cqx < 0) ? q1.x : q1.y;
        uint32_t p01 = (cqy < 0) ? q1.x : q1.z;
        uint32_t p11 = (cqy < 0) ? ((cqx < 0) ? q1.x : q1.y)
                                 : ((cqx < 0) ? q1.z : q1.w);

        float ff[8];
#pragma unroll
        for (int c = 0; c < 8; c++) {
            float s = fmaf(decu(p11, c), w11, base);
            s = fmaf(decu(p01, c), w01, s);
            s = fmaf(decu(p10, c), w10, s);
            s = fmaf(decu(p00, c), w00, s);
            ff[c] = s;
        }

        float* sf = &ffbuf[warp][lane][0];
        *(float4*)(sf + 0) = make_float4(ff[0], ff[1], ff[2], ff[3]);
        *(float4*)(sf + 4) = make_float4(ff[4], ff[5], ff[6], ff[7]);
        __syncwarp();   // codes (all lanes waited) + ff visible warp-wide

        // ---- coalesced readout ----
        const uint32_t* cw = &pbuf[cur][warp][0][0];
        const float* fw = &ffbuf[warp][0][0];
        float4* go = reinterpret_cast<float4*>(out) +
                     (size_t)(ptbase + it * 256 + warp * 32) * 10;
#pragma unroll
        for (int k = 0; k < 10; k++) {
            int wo = lane + 32 * k;
            int pp = wo / 10;
            int jj = wo - pp * 10;
            float4 v;
            if (jj < 8) {
                uint32_t code = cw[pp * 8 + (jj >> 1)];
                int cb = (jj & 1) * 4;
                v = make_float4(dec(code, cb), dec(code, cb + 1),
                                dec(code, cb + 2), dec(code, cb + 3));
            } else {
                v = *(const float4*)(fw + pp * 12 + (jj - 8) * 4);
            }
            __stcs(&go[wo], v);
        }
        __syncwarp();   // all lanes done reading before buffers are reused

        cix = nix; ciy = niy; cqx = nqx; cqy = nqy;
    }
}

extern "C" void kernel_launch(void* const* d_in, const int* in_sizes, int n_in,
                              void* d_out, int out_size) {
    const float2* uv = (const float2*)d_in[0];
    const float*  g0 = (const float*)d_in[1];
    const float*  g1 = (const float*)d_in[2];

    pack_all<<<NBLK0 + NBLK1, 512>>>(g0, g1);
    sample_kernel<<<NPTS / (256 * NITER), 256>>>(uv, (float*)d_out);
}

// round 17
// speedup vs baseline: 1.0920x; 1.0920x over previous
#include <cuda_runtime.h>
#include <cstdint>

#define RES0 2048
#define RES1 1024
#define NPTS 2097152

// g0: plain per-texel code table (8ch x 4bit -> u32). 16 MB.
__device__ uint32_t g_code0[(size_t)RES0 * RES0];
// g1: quad table, entry (y,x) = codes of 4 clamped corners. 16 MB.
__device__ uint4 g_quad1[(size_t)RES1 * RES1];
// Total 32 MB -> fully L2-resident against evict-first streams (proven R11).

// codes = clip(round((v + 15/32) * 16), 0, 15); round-half-even matches jnp.round.
__device__ __forceinline__ uint32_t quant_code(float v) {
    float t = __fmul_rn(__fadd_rn(v, 0.46875f), 16.0f);
    int c = __float2int_rn(t);
    return (uint32_t)max(0, min(15, c));
}

// Exact dequant of nibble i: c/16 - 15/32.
__device__ __forceinline__ float dec(uint32_t p, int i) {
    uint32_t t = (i < 5) ? (p << (19 - 4 * i)) : (p >> (4 * i - 19));
    uint32_t u = (t & 0x00780000u) | 0x3F800000u;
    return __uint_as_float(u) - 1.46875f;
}

// Partial dequant: 1 + c/16 (no subtraction).
__device__ __forceinline__ float decu(uint32_t p, int i) {
    uint32_t t = (i < 5) ? (p << (19 - 4 * i)) : (p >> (4 * i - 19));
    uint32_t u = (t & 0x00780000u) | 0x3F800000u;
    return __uint_as_float(u);
}

// ---------------- fused pack: both grids in ONE launch (R11, proven) --------
__device__ __forceinline__ void pack_body0(const float* __restrict__ g, int blk) {
    int i4 = (blk * 512 + threadIdx.x) * 4;
    uint32_t c0 = 0, c1 = 0, c2 = 0, c3 = 0;
#pragma unroll
    for (int ch = 0; ch < 8; ch++) {
        float4 v = __ldcs((const float4*)(g + (size_t)ch * RES0 * RES0 + i4));
        c0 |= quant_code(v.x) << (4 * ch);
        c1 |= quant_code(v.y) << (4 * ch);
        c2 |= quant_code(v.z) << (4 * ch);
        c3 |= quant_code(v.w) << (4 * ch);
    }
    *(uint4*)(g_code0 + i4) = make_uint4(c0, c1, c2, c3);
}

__device__ __forceinline__ void pack_body1(const float* __restrict__ g, int blk) {
    __shared__ uint32_t sc[17][33];
    int bx = (blk % (RES1 / 32)) * 32;
    int by = (blk / (RES1 / 32)) * 16;
    int tid = threadIdx.x;

    for (int p = tid; p < 17 * 33; p += 512) {
        int ly = p / 33, lx = p - ly * 33;
        int gx = min(bx + lx, RES1 - 1);
        int gy = min(by + ly, RES1 - 1);
        size_t base = (size_t)gy * RES1 + gx;
        uint32_t pk = 0;
#pragma unroll
        for (int c = 0; c < 8; c++) {
            float v = __ldcs(g + (size_t)c * RES1 * RES1 + base);
            pk |= quant_code(v) << (4 * c);
        }
        sc[ly][lx] = pk;
    }
    __syncthreads();

    int lx = tid & 31, ly = tid >> 5;
    g_quad1[(size_t)(by + ly) * RES1 + bx + lx] =
        make_uint4(sc[ly][lx], sc[ly][lx + 1], sc[ly + 1][lx], sc[ly + 1][lx + 1]);
}

#define NBLK0 (RES0 * RES0 / 4 / 512)       // 2048
#define NBLK1 ((RES1 / 32) * (RES1 / 16))   // 2048

__global__ __launch_bounds__(512) void pack_all(const float* __restrict__ g0,
                                                const float* __restrict__ g1) {
    int b = blockIdx.x;
    if (b < NBLK0) pack_body0(g0, b);
    else           pack_body1(g1, b - NBLK0);
}

// ---------------- sample: parity-predicated LDG.64 g0 gathers ---------------
__global__ __launch_bounds__(256) void sample_kernel(const float2* __restrict__ uv,
                                                     float* __restrict__ out) {
    __shared__ __align__(16) float sbuf[8 * 32 * 12];

    int tid = threadIdx.x;
    int lane = tid & 31;
    int warp = tid >> 5;
    int i = blockIdx.x * 256 + tid;

    float2 p = __ldcs(&uv[i]);

    // feat1 indices.
    float ix = fmaf(p.x, 1024.0f, -0.5f);
    float iy = fmaf(p.y, 1024.0f, -0.5f);
    float fx0 = floorf(ix), fy0 = floorf(iy);
    int qx0 = (int)fx0;
    int qy0 = (int)fy0;
    int cx = max(qx0, 0);
    int cy = max(qy0, 0);

    // feat0 indices: pos = uv*2048 - 0.5 ; x0 = clip(floor(pos), 0, 2046)
    float px = fmaf(p.x, 2048.0f, -0.5f);
    float py = fmaf(p.y, 2048.0f, -0.5f);
    int x0 = min(max((int)floorf(px), 0), RES0 - 2);
    int y0 = min(max((int)floorf(py), 0), RES0 - 2);

    // g0 gathers: per row, one ALIGNED LDG.64 always + one predicated on x0
    // odd (~half the lanes -> ~half the wavefronts of a full load).
    int e = x0 & ~1;                 // aligned pair base
    bool odd = (x0 & 1) != 0;
    const uint2* rowT = (const uint2*)(g_code0 + (size_t)y0 * RES0 + e);
    const uint2* rowB = (const uint2*)((const uint32_t*)rowT + RES0);

    uint4 q1 = __ldg(&g_quad1[(size_t)cy * RES1 + cx]);
    uint2 At = __ldg(rowT);
    uint2 Ab = __ldg(rowB);
    uint2 Bt = make_uint2(0u, 0u), Bb = make_uint2(0u, 0u);
    if (odd) {
        Bt = __ldg(rowT + 1);        // pair (x0+1, x0+2); x0+1 <= 2047 safe
        Bb = __ldg(rowB + 1);
    }
    uint32_t a00 = odd ? At.y : At.x;
    uint32_t a01 = odd ? Bt.x : At.y;
    uint32_t a10 = odd ? Ab.y : Ab.x;
    uint32_t a11 = odd ? Bb.x : Ab.y;

    // feat1 weights (zeros-padding via weight masking).
    float wx1 = __fsub_rn(ix, fx0), wx0 = __fsub_rn(1.0f, wx1);
    float wy1 = __fsub_rn(iy, fy0), wy0 = __fsub_rn(1.0f, wy1);
    float wx0m = (qx0 >= 0) ? wx0 : 0.0f;
    float wx1m = (qx0 + 1 <= RES1 - 1) ? wx1 : 0.0f;
    float wy0m = (qy0 >= 0) ? wy0 : 0.0f;
    float wy1m = (qy0 + 1 <= RES1 - 1) ? wy1 : 0.0f;
    float w00 = wx0m * wy0m;
    float w10 = wx1m * wy0m;
    float w01 = wx0m * wy1m;
    float w11 = wx1m * wy1m;
    // sum_c (u_i - k) w_i = sum u_i w_i - k * sum w_i ; base once per point.
    float wsum = ((w00 + w10) + w01) + w11;
    float base = -1.46875f * wsum;

    // Slot-select for clamped/OOB taps.
    uint32_t p00 = q1.x;
    uint32_t p10 = (qx0 < 0) ? q1.x : q1.y;
    uint32_t p01 = (qy0 < 0) ? q1.x : q1.z;
    uint32_t p11 = (qy0 < 0) ? ((qx0 < 0) ? q1.x : q1.y)
                             : ((qx0 < 0) ? q1.z : q1.w);

    // feat1: 8 channels, 4-FMA chain from base.
    float ff[8];
#pragma unroll
    for (int c = 0; c < 8; c++) {
        float s = fmaf(decu(p11, c), w11, base);
        s = fmaf(decu(p01, c), w01, s);
        s = fmaf(decu(p10, c), w10, s);
        s = fmaf(decu(p00, c), w00, s);
        ff[c] = s;
    }

    // Stage: raw g0 corner codes + decoded feat1 (3x STS.128 per point).
    float* s = &sbuf[warp * (32 * 12) + lane * 12];
    *(uint4*)s = make_uint4(a00, a01, a10, a11);
    *(float4*)(s + 4) = make_float4(ff[0], ff[1], ff[2], ff[3]);
    *(float4*)(s + 8) = make_float4(ff[4], ff[5], ff[6], ff[7]);
    __syncwarp();

    // Coalesced readout: decode feat0 nibbles on the fly.
    const float* ws = &sbuf[warp * (32 * 12)];
    float4* go = reinterpret_cast<float4*>(out) +
                 (size_t)(blockIdx.x * 256 + warp * 32) * 10;
#pragma unroll
    for (int k = 0; k < 10; k++) {
        int wo = lane + 32 * k;        // float4 index within the warp's 320
        int pp = wo / 10;              // point within warp tile
        int jj = wo - pp * 10;         // float4 within point
        const float* sp = ws + pp * 12;
        float4 v;
        if (jj < 8) {
            uint32_t code = __float_as_uint(sp[jj >> 1]);  // corner jj>>1
            int cb = (jj & 1) * 4;
            v = make_float4(dec(code, cb), dec(code, cb + 1),
                            dec(code, cb + 2), dec(code, cb + 3));
        } else {
            v = *(const float4*)(sp + 4 + (jj - 8) * 4);   // staged feat1
        }
        __stcs(&go[wo], v);
    }
}

extern "C" void kernel_launch(void* const* d_in, const int* in_sizes, int n_in,
                              void* d_out, int out_size) {
    const float2* uv = (const float2*)d_in[0];
    const float*  g0 = (const float*)d_in[1];
    const float*  g1 = (const float*)d_in[2];

    pack_all<<<NBLK0 + NBLK1, 512>>>(g0, g1);
    sample_kernel<<<NPTS / 256, 256>>>(uv, (float*)d_out);
}